// round 13
// baseline (speedup 1.0000x reference)
#include <cuda_runtime.h>
#include <cuda_fp16.h>
#include <cstdint>

#define TKN 8192   // tokens = 4*2048
#define NF  4096   // in features
#define OF  4096   // out features

// Scratch (static device globals -- allocation-free per harness rules)
__device__ __half g_x[(size_t)TKN * NF];    // 64 MB: fwht(input*SU)*scale, fp16
__device__ __half g_w[(size_t)OF * NF];     // 32 MB: W' = H*W, fp16
__device__ __half g_tmp[(size_t)OF * NF];   // 32 MB: W-FWHT intermediate

// ---------------------------------------------------------------------------
// Kernel 1: g_x[rowOff+blk] = fp16( fwht(input * SU) * Wscale/64 )
// ---------------------------------------------------------------------------
__global__ __launch_bounds__(256) void fwht_in_kernel(
        const float* __restrict__ in, const float* __restrict__ SU,
        const float* __restrict__ wscale, int rowOff) {
    __shared__ float s[4096];
    const int row = blockIdx.x + rowOff;
    const int tid = threadIdx.x;
    const int lane = tid & 31;

    float v[16];
    const float4* ip = (const float4*)(in + (size_t)row * NF + tid * 16);
    const float4* up = (const float4*)(SU + tid * 16);
    #pragma unroll
    for (int q = 0; q < 4; q++) {
        float4 a = ip[q], b = up[q];
        v[q*4+0] = a.x*b.x; v[q*4+1] = a.y*b.y;
        v[q*4+2] = a.z*b.z; v[q*4+3] = a.w*b.w;
    }

    #pragma unroll
    for (int h = 1; h < 16; h <<= 1)
        #pragma unroll
        for (int i = 0; i < 16; i++)
            if (!(i & h)) {
                float a = v[i], b = v[i ^ h];
                v[i] = a + b; v[i ^ h] = a - b;
            }
    #pragma unroll
    for (int d = 1; d < 16; d <<= 1) {
        #pragma unroll
        for (int r = 0; r < 16; r++) {
            float o = __shfl_xor_sync(0xffffffffu, v[r], d);
            v[r] = (lane & d) ? (o - v[r]) : (v[r] + o);
        }
    }
    float4* sv = (float4*)(s + tid * 16);
    sv[0] = make_float4(v[0], v[1], v[2], v[3]);
    sv[1] = make_float4(v[4], v[5], v[6], v[7]);
    sv[2] = make_float4(v[8], v[9], v[10], v[11]);
    sv[3] = make_float4(v[12], v[13], v[14], v[15]);
    __syncthreads();
    #pragma unroll
    for (int r = 0; r < 16; r++) v[r] = s[r * 256 + tid];
    #pragma unroll
    for (int h = 1; h < 16; h <<= 1)
        #pragma unroll
        for (int i = 0; i < 16; i++)
            if (!(i & h)) {
                float a = v[i], b = v[i ^ h];
                v[i] = a + b; v[i ^ h] = a - b;
            }

    const float sc = wscale[0] * 0.015625f;   // Wscale / sqrt(4096)
    __half* dst = g_x + (size_t)row * NF + tid;
    #pragma unroll
    for (int r = 0; r < 16; r++)
        dst[r * 256] = __float2half_rn(v[r] * sc);
}

// ---------------------------------------------------------------------------
// Kernel 2: fused dequant + FWHT pass 0 over output-dim bits 0..5.
// 128 threads/block, ONE half-lane per thread (high occupancy, R12 win).
// ---------------------------------------------------------------------------
__global__ __launch_bounds__(128) void wfwht0_kernel(
        const float* __restrict__ cb, const int* __restrict__ qidx) {
    __shared__ float scb[1024];               // cb: 256 codes x 4 floats = 4KB
    const int tid = threadIdx.x;
    ((float4*)scb)[tid]       = ((const float4*)cb)[tid];
    ((float4*)scb)[tid + 128] = ((const float4*)cb)[tid + 128];
    __syncthreads();

    const int b  = blockIdx.x;                // 0..63
    const int hc = blockIdx.y * 128 + tid;    // half-col (= input index i)
    const int qcol = hc >> 2;
    const int sub  = hc & 3;
    const int* qrow = qidx + (size_t)b * 64 * (NF / 4) + qcol;

    float v[64];
    #pragma unroll
    for (int r = 0; r < 64; r++) {
        int q = __ldg(qrow + (size_t)r * (NF / 4));
        v[r] = scb[q * 4 + sub];
    }

    #pragma unroll
    for (int h = 1; h < 64; h <<= 1)
        #pragma unroll
        for (int i = 0; i < 64; i++)
            if (!(i & h)) {
                float a = v[i], c = v[i ^ h];
                v[i] = a + c; v[i ^ h] = a - c;
            }

    __half* d = g_tmp + (size_t)b * 64 * NF + hc;
    #pragma unroll
    for (int r = 0; r < 64; r++)
        d[(size_t)r * NF] = __float2half_rn(v[r]);
}

// ---------------------------------------------------------------------------
// Kernel 2b: FWHT pass 1 over output-dim bits 6..11 (rows o = b + 64*r).
// ---------------------------------------------------------------------------
__global__ __launch_bounds__(128) void wfwht1_kernel() {
    const int b  = blockIdx.x;                // 0..63
    const int hc = blockIdx.y * 128 + threadIdx.x;
    const __half* s = g_tmp + (size_t)b * NF + hc;
    __half*       d = g_w   + (size_t)b * NF + hc;
    const size_t rstep = (size_t)64 * NF;

    float v[64];
    #pragma unroll
    for (int r = 0; r < 64; r++)
        v[r] = __half2float(__ldg(s + r * rstep));

    #pragma unroll
    for (int h = 1; h < 64; h <<= 1)
        #pragma unroll
        for (int i = 0; i < 64; i++)
            if (!(i & h)) {
                float a = v[i], c = v[i ^ h];
                v[i] = a + c; v[i ^ h] = a - c;
            }

    #pragma unroll
    for (int r = 0; r < 64; r++)
        d[r * rstep] = __float2half_rn(v[r]);
}

// ---------------------------------------------------------------------------
// Kernel 3: fp16 mma.sync GEMM + fused epilogue.  R8 mainloop FROZEN
// (tensor=74% is the sm_103a mma.sync ceiling, invariant R8/R9/R11).
// mOff slices the token dimension for cross-stream overlap.
// ---------------------------------------------------------------------------
#define BM 256
#define BN 128
#define BKH 128                      // halves per k-stage (256 bytes, 2 sub-tiles)
#define KITERS (NF / BKH)            // 32
#define A_HALF_B (BM * 128)          // 32768
#define B_HALF_B (BN * 128)          // 16384
#define A_TILE_B (2 * A_HALF_B)      // 65536
#define B_TILE_B (2 * B_HALF_B)      // 32768
#define STAGE_B  (A_TILE_B + B_TILE_B)      // 98304
#define GEMM_SMEM (2 * STAGE_B)             // 196608

__device__ __forceinline__ uint32_t sw128(uint32_t o) { return o ^ ((o >> 3) & 0x70); }

__device__ __forceinline__ void cpa(uint32_t dst, const void* src) {
    asm volatile("cp.async.cg.shared.global [%0], [%1], 16;" :: "r"(dst), "l"(src));
}

__device__ __forceinline__ void ldsm4(uint32_t* r, uint32_t addr) {
    asm volatile("ldmatrix.sync.aligned.m8n8.x4.shared.b16 {%0,%1,%2,%3}, [%4];"
                 : "=r"(r[0]), "=r"(r[1]), "=r"(r[2]), "=r"(r[3]) : "r"(addr));
}

__device__ __forceinline__ void load_stage(uint32_t base, int st, int mBase,
                                           int nBase, int tid) {
    const int k0 = st * BKH;
    const __half* A = g_x + (size_t)mBase * NF + k0;
    const __half* B = g_w + (size_t)nBase * NF + k0;
    #pragma unroll
    for (int i = 0; i < 16; i++) {                // A: 4096 x 16B
        int id = tid + (i << 8);
        int r = id >> 4, c16 = id & 15;
        cpa(base + (c16 >> 3) * A_HALF_B + sw128(r * 128 + (c16 & 7) * 16),
            A + (size_t)r * NF + c16 * 8);
    }
    #pragma unroll
    for (int i = 0; i < 8; i++) {                 // B: 2048 x 16B
        int id = tid + (i << 8);
        int r = id >> 4, c16 = id & 15;
        cpa(base + A_TILE_B + (c16 >> 3) * B_HALF_B + sw128(r * 128 + (c16 & 7) * 16),
            B + (size_t)r * NF + c16 * 8);
    }
    asm volatile("cp.async.commit_group;");
}

__global__ __launch_bounds__(256, 1) void gemm_f16_kernel(
        const float* __restrict__ SV, const float* __restrict__ bias,
        float* __restrict__ out, int mOff) {
    extern __shared__ __align__(1024) uint8_t sm[];
    const uint32_t smem_base = (uint32_t)__cvta_generic_to_shared(sm);

    const int tid  = threadIdx.x;
    const int warp = tid >> 5, lane = tid & 31;
    const int wm = warp >> 1, wn = warp & 1;       // 4 x 2 warp grid, 64x64 tiles
    const int g  = lane >> 2, t = lane & 3;
    const int mBase = blockIdx.y * BM + mOff;
    const int nBase = blockIdx.x * BN;

    // ldmatrix lane addressing
    const int a_row  = lane & 15;
    const int a_koff = (lane >> 4) * 16;           // 0/16 bytes
    const int b_row  = (lane & 7) + ((lane >> 4) & 1) * 8;
    const int b_koff = ((lane >> 3) & 1) * 16;

    uint32_t aBase[4], aXor[4], bBase[4], bXor[4];
    #pragma unroll
    for (int mt = 0; mt < 4; mt++) {
        uint32_t rb = (wm * 64 + mt * 16 + a_row) * 128;
        aBase[mt] = rb; aXor[mt] = (rb >> 3) & 0x70;
    }
    #pragma unroll
    for (int np = 0; np < 4; np++) {
        uint32_t rb = (wn * 64 + np * 16 + b_row) * 128;
        bBase[np] = rb; bXor[np] = (rb >> 3) & 0x70;
    }

    float acc[4][8][4];
    #pragma unroll
    for (int a = 0; a < 4; a++)
        #pragma unroll
        for (int b = 0; b < 8; b++)
            #pragma unroll
            for (int c = 0; c < 4; c++) acc[a][b][c] = 0.f;

    load_stage(smem_base, 0, mBase, nBase, tid);

    for (int s = 0; s < KITERS; s++) {
        asm volatile("cp.async.wait_group 0;" ::: "memory");
        __syncthreads();
        if (s + 1 < KITERS)
            load_stage(smem_base + ((s + 1) & 1) * STAGE_B, s + 1,
                       mBase, nBase, tid);

        const uint32_t As = smem_base + (s & 1) * STAGE_B;
        const uint32_t Bs = As + A_TILE_B;

        uint32_t af[2][4][4], bf[2][4][4];
        #pragma unroll
        for (int mt = 0; mt < 4; mt++)
            ldsm4(af[0][mt], As + aBase[mt] + (a_koff ^ aXor[mt]));
        #pragma unroll
        for (int np = 0; np < 4; np++)
            ldsm4(bf[0][np], Bs + bBase[np] + (b_koff ^ bXor[np]));

        #pragma unroll
        for (int kc = 0; kc < 8; kc++) {           // 8 k-chunks of 16
            const int cur = kc & 1, nxt = cur ^ 1;
            if (kc < 7) {
                const int kn = kc + 1;
                const uint32_t ah = As + (kn >> 2) * A_HALF_B;
                const uint32_t bh = Bs + (kn >> 2) * B_HALF_B;
                const uint32_t ak = (kn & 3) * 32 + a_koff;
                const uint32_t bk = (kn & 3) * 32 + b_koff;
                #pragma unroll
                for (int mt = 0; mt < 4; mt++)
                    ldsm4(af[nxt][mt], ah + aBase[mt] + (ak ^ aXor[mt]));
                #pragma unroll
                for (int np = 0; np < 4; np++)
                    ldsm4(bf[nxt][np], bh + bBase[np] + (bk ^ bXor[np]));
            }
            #pragma unroll
            for (int mt = 0; mt < 4; mt++)
                #pragma unroll
                for (int nt = 0; nt < 8; nt++) {
                    float* c = acc[mt][nt];
                    const uint32_t b0 = bf[cur][nt >> 1][(nt & 1) * 2 + 0];
                    const uint32_t b1 = bf[cur][nt >> 1][(nt & 1) * 2 + 1];
                    asm volatile(
                        "mma.sync.aligned.m16n8k16.row.col.f32.f16.f16.f32 "
                        "{%0,%1,%2,%3}, {%4,%5,%6,%7}, {%8,%9}, {%0,%1,%2,%3};"
                        : "+f"(c[0]), "+f"(c[1]), "+f"(c[2]), "+f"(c[3])
                        : "r"(af[cur][mt][0]), "r"(af[cur][mt][1]),
                          "r"(af[cur][mt][2]), "r"(af[cur][mt][3]),
                          "r"(b0), "r"(b1));
                }
        }
        // no bottom barrier: top barrier of next iter orders compute(s)
        // before the cp.async overwrite of buffer s&1 (issued at iter s+1).
    }

    // Fused epilogue: out = acc/64 * SV + bias
    const float isq = 0.015625f;   // 1/sqrt(4096)
    #pragma unroll
    for (int nt = 0; nt < 8; nt++) {
        const int c0 = nBase + wn * 64 + nt * 8 + (t << 1);
        const float sv0 = __ldg(SV + c0)     * isq;
        const float sv1 = __ldg(SV + c0 + 1) * isq;
        const float bb0 = __ldg(bias + c0);
        const float bb1 = __ldg(bias + c0 + 1);
        #pragma unroll
        for (int mt = 0; mt < 4; mt++) {
            const int r0 = mBase + wm * 64 + mt * 16 + g;
            float* c = acc[mt][nt];
            *(float2*)(out + (size_t)r0 * OF + c0) =
                make_float2(c[0] * sv0 + bb0, c[1] * sv1 + bb1);
            *(float2*)(out + (size_t)(r0 + 8) * OF + c0) =
                make_float2(c[2] * sv0 + bb0, c[3] * sv1 + bb1);
        }
    }
}

// ---------------------------------------------------------------------------
// Launch graph (token-sliced overlap):
//   main:  fwht_in[0:4096)            -> (wait W) gemm[0:4096)
//   side:  wfwht0 -> wfwht1 -> fwht_in[4096:8192) -> gemm[4096:8192)
// The side-stream FWHT+W kernels (memory-bound, tensor=0) overlap with
// gemm-half0 (tensor=74%, DRAM=5%); the two 512-CTA GEMMs co-pack across
// streams so there is no wave-quantization penalty.
// ---------------------------------------------------------------------------
#define MHALF (TKN / 2)

extern "C" void kernel_launch(void* const* d_in, const int* in_sizes, int n_in,
                              void* d_out, int out_size) {
    const float* input  = (const float*)d_in[0];
    const float* SU     = (const float*)d_in[1];
    const float* SV     = (const float*)d_in[2];
    const float* cb     = (const float*)d_in[3];
    const int*   Qidxs  = (const int*)d_in[4];
    const float* Wscale = (const float*)d_in[5];
    const float* bias   = (const float*)d_in[6];
    float* out = (float*)d_out;

    cudaFuncSetAttribute(gemm_f16_kernel,
                         cudaFuncAttributeMaxDynamicSharedMemorySize, GEMM_SMEM);

    cudaStream_t side;
    cudaStreamCreateWithFlags(&side, cudaStreamNonBlocking);
    cudaEvent_t evFork, evW, evJ;
    cudaEventCreateWithFlags(&evFork, cudaEventDisableTiming);
    cudaEventCreateWithFlags(&evW,    cudaEventDisableTiming);
    cudaEventCreateWithFlags(&evJ,    cudaEventDisableTiming);

    // Fork side stream off the captured origin stream.
    cudaEventRecord(evFork, 0);
    cudaStreamWaitEvent(side, evFork, 0);

    // main: x-FWHT for token half 0
    fwht_in_kernel<<<MHALF, 256>>>(input, SU, Wscale, 0);

    // side: W' = H*W, then x-FWHT half 1, then GEMM half 1
    wfwht0_kernel<<<dim3(64, NF / 128), 128, 0, side>>>(cb, Qidxs);
    wfwht1_kernel<<<dim3(64, NF / 128), 128, 0, side>>>();
    cudaEventRecord(evW, side);                       // W' ready
    fwht_in_kernel<<<MHALF, 256, 0, side>>>(input, SU, Wscale, MHALF);
    gemm_f16_kernel<<<dim3(OF / BN, MHALF / BM), 256, GEMM_SMEM, side>>>(
        SV, bias, out, MHALF);

    // main: GEMM half 0 (needs half-0 x (program order) + W' (event))
    cudaStreamWaitEvent(0, evW, 0);
    gemm_f16_kernel<<<dim3(OF / BN, MHALF / BM), 256, GEMM_SMEM>>>(
        SV, bias, out, 0);

    // join side branch back into the origin stream
    cudaEventRecord(evJ, side);
    cudaStreamWaitEvent(0, evJ, 0);
    // Stream/event handles are host objects; bounded leak (correctness +
    // capture calls only), no device memory touched.
}

// round 14
// speedup vs baseline: 1.0399x; 1.0399x over previous
#include <cuda_runtime.h>
#include <cuda_fp16.h>
#include <cstdint>

#define TKN 8192   // tokens = 4*2048
#define NF  4096   // in features
#define OF  4096   // out features

// Scratch (static device globals -- allocation-free per harness rules)
__device__ __half g_x[(size_t)TKN * NF];    // 64 MB: fwht(input*SU)*scale, fp16
__device__ __half g_w[(size_t)OF * NF];     // 32 MB: W' = H*W, fp16
__device__ __half g_tmp[(size_t)OF * NF];   // 32 MB: W-FWHT intermediate

// ---------------------------------------------------------------------------
// Kernel 1: g_x = fp16( fwht(input * SU) * Wscale/64 )
// Shuffle-free FWHT: 3 register views x 4 bits, two padded-smem transposes.
//   view1: i = tid*16 + r          (bits 0-3 in regs)
//   view2: i = hi*256 + r*16 + lo  (bits 4-7 in regs)   hi=tid>>4, lo=tid&15
//   view3: i = r*256 + tid         (bits 8-11 in regs, coalesced stores)
// pad(i) = i + (i>>4): T1w s[tid*17+r], T1r s[hi*272+r*17+lo] (both
// conflict-free, gcd(17,32)=1); T2 writes back the same per-thread addresses
// (no barrier needed); T2r s[r*272+tid+hi] (single 2-way conflict pair).
// ---------------------------------------------------------------------------
__global__ __launch_bounds__(256) void fwht_in_kernel(
        const float* __restrict__ in, const float* __restrict__ SU,
        const float* __restrict__ wscale) {
    __shared__ float s[4096 + 256];
    const int row = blockIdx.x;
    const int tid = threadIdx.x;
    const int hi = tid >> 4, lo = tid & 15;

    float v[16];
    const float4* ip = (const float4*)(in + (size_t)row * NF + tid * 16);
    const float4* up = (const float4*)(SU + tid * 16);
    #pragma unroll
    for (int q = 0; q < 4; q++) {
        float4 a = ip[q], b = up[q];
        v[q*4+0] = a.x*b.x; v[q*4+1] = a.y*b.y;
        v[q*4+2] = a.z*b.z; v[q*4+3] = a.w*b.w;
    }

    // bits 0-3 (view1 regs)
    #pragma unroll
    for (int h = 1; h < 16; h <<= 1)
        #pragma unroll
        for (int i = 0; i < 16; i++)
            if (!(i & h)) {
                float a = v[i], b = v[i ^ h];
                v[i] = a + b; v[i ^ h] = a - b;
            }

    // transpose 1: view1 -> view2
    #pragma unroll
    for (int r = 0; r < 16; r++) s[tid * 17 + r] = v[r];
    __syncthreads();
    #pragma unroll
    for (int r = 0; r < 16; r++) v[r] = s[hi * 272 + r * 17 + lo];

    // bits 4-7 (view2 regs)
    #pragma unroll
    for (int h = 1; h < 16; h <<= 1)
        #pragma unroll
        for (int i = 0; i < 16; i++)
            if (!(i & h)) {
                float a = v[i], b = v[i ^ h];
                v[i] = a + b; v[i ^ h] = a - b;
            }

    // transpose 2: view2 -> view3 (write-back to same per-thread addresses)
    #pragma unroll
    for (int r = 0; r < 16; r++) s[hi * 272 + r * 17 + lo] = v[r];
    __syncthreads();
    #pragma unroll
    for (int r = 0; r < 16; r++) v[r] = s[r * 272 + tid + hi];

    // bits 8-11 (view3 regs)
    #pragma unroll
    for (int h = 1; h < 16; h <<= 1)
        #pragma unroll
        for (int i = 0; i < 16; i++)
            if (!(i & h)) {
                float a = v[i], b = v[i ^ h];
                v[i] = a + b; v[i ^ h] = a - b;
            }

    const float sc = wscale[0] * 0.015625f;   // Wscale / sqrt(4096)
    __half* dst = g_x + (size_t)row * NF + tid;
    #pragma unroll
    for (int r = 0; r < 16; r++)
        dst[r * 256] = __float2half_rn(v[r] * sc);
}

// ---------------------------------------------------------------------------
// Kernel 2: fused dequant + FWHT pass 0 over output-dim bits 0..5.
// 128 threads/block, ONE half-lane per thread (high occupancy, R12 win).
// ---------------------------------------------------------------------------
__global__ __launch_bounds__(128) void wfwht0_kernel(
        const float* __restrict__ cb, const int* __restrict__ qidx) {
    __shared__ float scb[1024];               // cb: 256 codes x 4 floats = 4KB
    const int tid = threadIdx.x;
    ((float4*)scb)[tid]       = ((const float4*)cb)[tid];
    ((float4*)scb)[tid + 128] = ((const float4*)cb)[tid + 128];
    __syncthreads();

    const int b  = blockIdx.x;                // 0..63
    const int hc = blockIdx.y * 128 + tid;    // half-col (= input index i)
    const int qcol = hc >> 2;
    const int sub  = hc & 3;
    const int* qrow = qidx + (size_t)b * 64 * (NF / 4) + qcol;

    float v[64];
    #pragma unroll
    for (int r = 0; r < 64; r++) {
        int q = __ldg(qrow + (size_t)r * (NF / 4));
        v[r] = scb[q * 4 + sub];
    }

    #pragma unroll
    for (int h = 1; h < 64; h <<= 1)
        #pragma unroll
        for (int i = 0; i < 64; i++)
            if (!(i & h)) {
                float a = v[i], c = v[i ^ h];
                v[i] = a + c; v[i ^ h] = a - c;
            }

    __half* d = g_tmp + (size_t)b * 64 * NF + hc;
    #pragma unroll
    for (int r = 0; r < 64; r++)
        d[(size_t)r * NF] = __float2half_rn(v[r]);
}

// ---------------------------------------------------------------------------
// Kernel 2b: FWHT pass 1 over output-dim bits 6..11 (rows o = b + 64*r).
// ---------------------------------------------------------------------------
__global__ __launch_bounds__(128) void wfwht1_kernel() {
    const int b  = blockIdx.x;                // 0..63
    const int hc = blockIdx.y * 128 + threadIdx.x;
    const __half* s = g_tmp + (size_t)b * NF + hc;
    __half*       d = g_w   + (size_t)b * NF + hc;
    const size_t rstep = (size_t)64 * NF;

    float v[64];
    #pragma unroll
    for (int r = 0; r < 64; r++)
        v[r] = __half2float(__ldg(s + r * rstep));

    #pragma unroll
    for (int h = 1; h < 64; h <<= 1)
        #pragma unroll
        for (int i = 0; i < 64; i++)
            if (!(i & h)) {
                float a = v[i], c = v[i ^ h];
                v[i] = a + c; v[i ^ h] = a - c;
            }

    #pragma unroll
    for (int r = 0; r < 64; r++)
        d[r * rstep] = __float2half_rn(v[r]);
}

// ---------------------------------------------------------------------------
// Kernel 3: fp16 mma.sync GEMM + fused epilogue.  R8 configuration, FROZEN
// (tensor=74% is the sm_103a mma.sync dispatch ceiling, invariant across
// R8/R9/R11 schedule variants — do not touch).
// ---------------------------------------------------------------------------
#define BM 256
#define BN 128
#define BKH 128                      // halves per k-stage (256 bytes, 2 sub-tiles)
#define KITERS (NF / BKH)            // 32
#define A_HALF_B (BM * 128)          // 32768
#define B_HALF_B (BN * 128)          // 16384
#define A_TILE_B (2 * A_HALF_B)      // 65536
#define B_TILE_B (2 * B_HALF_B)      // 32768
#define STAGE_B  (A_TILE_B + B_TILE_B)      // 98304
#define GEMM_SMEM (2 * STAGE_B)             // 196608

__device__ __forceinline__ uint32_t sw128(uint32_t o) { return o ^ ((o >> 3) & 0x70); }

__device__ __forceinline__ void cpa(uint32_t dst, const void* src) {
    asm volatile("cp.async.cg.shared.global [%0], [%1], 16;" :: "r"(dst), "l"(src));
}

__device__ __forceinline__ void ldsm4(uint32_t* r, uint32_t addr) {
    asm volatile("ldmatrix.sync.aligned.m8n8.x4.shared.b16 {%0,%1,%2,%3}, [%4];"
                 : "=r"(r[0]), "=r"(r[1]), "=r"(r[2]), "=r"(r[3]) : "r"(addr));
}

__device__ __forceinline__ void load_stage(uint32_t base, int st, int mBase,
                                           int nBase, int tid) {
    const int k0 = st * BKH;
    const __half* A = g_x + (size_t)mBase * NF + k0;
    const __half* B = g_w + (size_t)nBase * NF + k0;
    #pragma unroll
    for (int i = 0; i < 16; i++) {                // A: 4096 x 16B
        int id = tid + (i << 8);
        int r = id >> 4, c16 = id & 15;
        cpa(base + (c16 >> 3) * A_HALF_B + sw128(r * 128 + (c16 & 7) * 16),
            A + (size_t)r * NF + c16 * 8);
    }
    #pragma unroll
    for (int i = 0; i < 8; i++) {                 // B: 2048 x 16B
        int id = tid + (i << 8);
        int r = id >> 4, c16 = id & 15;
        cpa(base + A_TILE_B + (c16 >> 3) * B_HALF_B + sw128(r * 128 + (c16 & 7) * 16),
            B + (size_t)r * NF + c16 * 8);
    }
    asm volatile("cp.async.commit_group;");
}

__global__ __launch_bounds__(256, 1) void gemm_f16_kernel(
        const float* __restrict__ SV, const float* __restrict__ bias,
        float* __restrict__ out) {
    extern __shared__ __align__(1024) uint8_t sm[];
    const uint32_t smem_base = (uint32_t)__cvta_generic_to_shared(sm);

    const int tid  = threadIdx.x;
    const int warp = tid >> 5, lane = tid & 31;
    const int wm = warp >> 1, wn = warp & 1;       // 4 x 2 warp grid, 64x64 tiles
    const int g  = lane >> 2, t = lane & 3;
    const int mBase = blockIdx.y * BM;
    const int nBase = blockIdx.x * BN;

    // ldmatrix lane addressing
    const int a_row  = lane & 15;
    const int a_koff = (lane >> 4) * 16;           // 0/16 bytes
    const int b_row  = (lane & 7) + ((lane >> 4) & 1) * 8;
    const int b_koff = ((lane >> 3) & 1) * 16;

    uint32_t aBase[4], aXor[4], bBase[4], bXor[4];
    #pragma unroll
    for (int mt = 0; mt < 4; mt++) {
        uint32_t rb = (wm * 64 + mt * 16 + a_row) * 128;
        aBase[mt] = rb; aXor[mt] = (rb >> 3) & 0x70;
    }
    #pragma unroll
    for (int np = 0; np < 4; np++) {
        uint32_t rb = (wn * 64 + np * 16 + b_row) * 128;
        bBase[np] = rb; bXor[np] = (rb >> 3) & 0x70;
    }

    float acc[4][8][4];
    #pragma unroll
    for (int a = 0; a < 4; a++)
        #pragma unroll
        for (int b = 0; b < 8; b++)
            #pragma unroll
            for (int c = 0; c < 4; c++) acc[a][b][c] = 0.f;

    load_stage(smem_base, 0, mBase, nBase, tid);

    for (int s = 0; s < KITERS; s++) {
        asm volatile("cp.async.wait_group 0;" ::: "memory");
        __syncthreads();
        if (s + 1 < KITERS)
            load_stage(smem_base + ((s + 1) & 1) * STAGE_B, s + 1,
                       mBase, nBase, tid);

        const uint32_t As = smem_base + (s & 1) * STAGE_B;
        const uint32_t Bs = As + A_TILE_B;

        uint32_t af[2][4][4], bf[2][4][4];
        #pragma unroll
        for (int mt = 0; mt < 4; mt++)
            ldsm4(af[0][mt], As + aBase[mt] + (a_koff ^ aXor[mt]));
        #pragma unroll
        for (int np = 0; np < 4; np++)
            ldsm4(bf[0][np], Bs + bBase[np] + (b_koff ^ bXor[np]));

        #pragma unroll
        for (int kc = 0; kc < 8; kc++) {           // 8 k-chunks of 16
            const int cur = kc & 1, nxt = cur ^ 1;
            if (kc < 7) {
                const int kn = kc + 1;
                const uint32_t ah = As + (kn >> 2) * A_HALF_B;
                const uint32_t bh = Bs + (kn >> 2) * B_HALF_B;
                const uint32_t ak = (kn & 3) * 32 + a_koff;
                const uint32_t bk = (kn & 3) * 32 + b_koff;
                #pragma unroll
                for (int mt = 0; mt < 4; mt++)
                    ldsm4(af[nxt][mt], ah + aBase[mt] + (ak ^ aXor[mt]));
                #pragma unroll
                for (int np = 0; np < 4; np++)
                    ldsm4(bf[nxt][np], bh + bBase[np] + (bk ^ bXor[np]));
            }
            #pragma unroll
            for (int mt = 0; mt < 4; mt++)
                #pragma unroll
                for (int nt = 0; nt < 8; nt++) {
                    float* c = acc[mt][nt];
                    const uint32_t b0 = bf[cur][nt >> 1][(nt & 1) * 2 + 0];
                    const uint32_t b1 = bf[cur][nt >> 1][(nt & 1) * 2 + 1];
                    asm volatile(
                        "mma.sync.aligned.m16n8k16.row.col.f32.f16.f16.f32 "
                        "{%0,%1,%2,%3}, {%4,%5,%6,%7}, {%8,%9}, {%0,%1,%2,%3};"
                        : "+f"(c[0]), "+f"(c[1]), "+f"(c[2]), "+f"(c[3])
                        : "r"(af[cur][mt][0]), "r"(af[cur][mt][1]),
                          "r"(af[cur][mt][2]), "r"(af[cur][mt][3]),
                          "r"(b0), "r"(b1));
                }
        }
        // no bottom barrier: top barrier of next iter orders compute(s)
        // before the cp.async overwrite of buffer s&1 (issued at iter s+1).
    }

    // Fused epilogue: out = acc/64 * SV + bias
    const float isq = 0.015625f;   // 1/sqrt(4096)
    #pragma unroll
    for (int nt = 0; nt < 8; nt++) {
        const int c0 = nBase + wn * 64 + nt * 8 + (t << 1);
        const float sv0 = __ldg(SV + c0)     * isq;
        const float sv1 = __ldg(SV + c0 + 1) * isq;
        const float bb0 = __ldg(bias + c0);
        const float bb1 = __ldg(bias + c0 + 1);
        #pragma unroll
        for (int mt = 0; mt < 4; mt++) {
            const int r0 = mBase + wm * 64 + mt * 16 + g;
            float* c = acc[mt][nt];
            *(float2*)(out + (size_t)r0 * OF + c0) =
                make_float2(c[0] * sv0 + bb0, c[1] * sv1 + bb1);
            *(float2*)(out + (size_t)(r0 + 8) * OF + c0) =
                make_float2(c[2] * sv0 + bb0, c[3] * sv1 + bb1);
        }
    }
}

// ---------------------------------------------------------------------------
// Launch: serial (R12 structure — stream overlap measured neutral/regressive
// in R10/R13, abandoned).
// ---------------------------------------------------------------------------
extern "C" void kernel_launch(void* const* d_in, const int* in_sizes, int n_in,
                              void* d_out, int out_size) {
    const float* input  = (const float*)d_in[0];
    const float* SU     = (const float*)d_in[1];
    const float* SV     = (const float*)d_in[2];
    const float* cb     = (const float*)d_in[3];
    const int*   Qidxs  = (const int*)d_in[4];
    const float* Wscale = (const float*)d_in[5];
    const float* bias   = (const float*)d_in[6];
    float* out = (float*)d_out;

    cudaFuncSetAttribute(gemm_f16_kernel,
                         cudaFuncAttributeMaxDynamicSharedMemorySize, GEMM_SMEM);

    fwht_in_kernel<<<TKN, 256>>>(input, SU, Wscale);
    // W' = H * W  (FWHT along output dim; pass 0 fused with codebook dequant)
    wfwht0_kernel<<<dim3(64, NF / 128), 128>>>(cb, Qidxs);
    wfwht1_kernel<<<dim3(64, NF / 128), 128>>>();
    gemm_f16_kernel<<<dim3(OF / BN, TKN / BM), 256, GEMM_SMEM>>>(SV, bias, out);
}